// round 1
// baseline (speedup 1.0000x reference)
#include <cuda_runtime.h>
#include <math.h>

#define B_   2
#define T_   2048
#define C_   768
#define H_   12
#define HS_  64
#define M_TOT (B_*T_)            // 4096
#define SCALE_F 0.03608439182435161f   // 1/sqrt(768)

// ---------------- scratch (device globals; no allocations allowed) ----------
__device__ float g_u[B_*H_*T_*HS_];   // queries, [b,h,t,hs]
__device__ float g_v[B_*H_*T_*HS_];   // values,  [b,h,t,hs]
__device__ float g_y[B_*T_*C_];       // attn output, [b,t,c]

// ---------------------------------------------------------------------------
// SGEMM: out = A[M,K] @ W[N,K]^T + bias,  M=4096, N=K=768
// Block tile 64(M) x 128(N), BK=8, 256 threads, thread tile 4x8.
// MODE 0 -> write g_u in [b,h,t,hs]; MODE 1 -> g_v same; MODE 2 -> A=g_y, plain out.
// ---------------------------------------------------------------------------
template<int MODE>
__global__ __launch_bounds__(256)
void gemm_xwT_kernel(const float* __restrict__ A, const float* __restrict__ W,
                     const float* __restrict__ bias, float* __restrict__ outp)
{
    const int K = C_, N = C_;
    __shared__ float As[8*68];    // [kk][64 rows + pad]
    __shared__ float Bs[8*132];   // [kk][128 cols + pad]

    const int tid = threadIdx.x;
    const int tx = tid & 15, ty = tid >> 4;
    const int m0 = blockIdx.y * 64;
    const int n0 = blockIdx.x * 128;

    const float* Ap = (MODE == 2) ? (const float*)g_y : A;

    // load indices
    const int arow = tid >> 1;            // 0..127 (A uses only tid<128 -> 0..63)
    const int acol4 = (tid & 1) * 4;

    float acc[4][8];
    #pragma unroll
    for (int i = 0; i < 4; i++)
        #pragma unroll
        for (int j = 0; j < 8; j++) acc[i][j] = 0.f;

    const float* AptrBase = Ap + (size_t)(m0 + arow) * K + acol4;   // valid if tid<128
    const float* WptrBase = W  + (size_t)(n0 + arow) * K + acol4;

    for (int k0 = 0; k0 < K; k0 += 8) {
        float4 a4 = make_float4(0.f,0.f,0.f,0.f);
        if (tid < 128) a4 = *reinterpret_cast<const float4*>(AptrBase + k0);
        float4 b4 = *reinterpret_cast<const float4*>(WptrBase + k0);

        __syncthreads();   // previous compute done reading smem
        if (tid < 128) {
            As[(acol4+0)*68 + arow] = a4.x;
            As[(acol4+1)*68 + arow] = a4.y;
            As[(acol4+2)*68 + arow] = a4.z;
            As[(acol4+3)*68 + arow] = a4.w;
        }
        Bs[(acol4+0)*132 + arow] = b4.x;
        Bs[(acol4+1)*132 + arow] = b4.y;
        Bs[(acol4+2)*132 + arow] = b4.z;
        Bs[(acol4+3)*132 + arow] = b4.w;
        __syncthreads();

        #pragma unroll
        for (int kk = 0; kk < 8; kk++) {
            float4 a0 = *reinterpret_cast<const float4*>(&As[kk*68 + ty*4]);
            float4 b0 = *reinterpret_cast<const float4*>(&Bs[kk*132 + tx*4]);
            float4 b1 = *reinterpret_cast<const float4*>(&Bs[kk*132 + tx*4 + 64]);
            float ra[4] = {a0.x, a0.y, a0.z, a0.w};
            float rb[8] = {b0.x, b0.y, b0.z, b0.w, b1.x, b1.y, b1.z, b1.w};
            #pragma unroll
            for (int i = 0; i < 4; i++)
                #pragma unroll
                for (int j = 0; j < 8; j++)
                    acc[i][j] = fmaf(ra[i], rb[j], acc[i][j]);
        }
    }

    // epilogue
    #pragma unroll
    for (int i = 0; i < 4; i++) {
        const int m = m0 + ty*4 + i;
        #pragma unroll
        for (int jh = 0; jh < 2; jh++) {
            #pragma unroll
            for (int j = 0; j < 4; j++) {
                const int n = n0 + jh*64 + tx*4 + j;
                const float v = acc[i][jh*4 + j] + bias[n];
                if (MODE == 2) {
                    outp[(size_t)m * N + n] = v;
                } else {
                    const int b = m >> 11, t = m & (T_-1);
                    const int h = n >> 6,  hs = n & 63;
                    float* dst = (MODE == 0) ? g_u : g_v;
                    dst[(((size_t)(b*H_ + h))*T_ + t)*HS_ + hs] = v;
                }
            }
        }
    }
}

// ---------------------------------------------------------------------------
// Flash attention, fp32. Q tile 128 rows, K/V tiles 128, HS=64.
// grid (16 q-tiles, 24 b*h), 256 threads. Causal: iterate kt <= qt only.
// ---------------------------------------------------------------------------
#define ATTN_SMEM_FLOATS (64*132 + 64*132 + 128*64 + 128*132)
#define ATTN_SMEM_BYTES  (ATTN_SMEM_FLOATS * 4)

__global__ __launch_bounds__(256, 1)
void attn_kernel(const float* __restrict__ x)
{
    extern __shared__ float smem[];
    float* Qs = smem;                  // [d(64)][r(128)+pad] stride 132
    float* Ks = Qs + 64*132;           // [d(64)][c(128)+pad] stride 132
    float* Vs = Ks + 64*132;           // [k(128)][d(64)]
    float* Ps = Vs + 128*64;           // [r(128)][k(128)+pad] stride 132

    const int tid = threadIdx.x;
    const int tx = tid & 15, ty = tid >> 4;
    const int c0 = tx * 4;

    const int qt = (int)(gridDim.x - 1) - (int)blockIdx.x;  // longest work first
    const int bh = blockIdx.y;
    const int b = bh / H_, h = bh % H_;
    const int q0 = qt * 128;

    const float* uBase = g_u + (size_t)bh * T_ * HS_;
    const float* vBase = g_v + (size_t)bh * T_ * HS_;
    const float* xBase = x + (size_t)b * T_ * C_ + h * HS_;

    // load Q tile (scaled), transposed to [d][r]
    #pragma unroll
    for (int it = 0; it < 8; it++) {
        const int f = tid + it*256;
        const int r = f >> 4;
        const int d4 = (f & 15) * 4;
        float4 q4 = *reinterpret_cast<const float4*>(uBase + (size_t)(q0 + r)*HS_ + d4);
        Qs[(d4+0)*132 + r] = q4.x * SCALE_F;
        Qs[(d4+1)*132 + r] = q4.y * SCALE_F;
        Qs[(d4+2)*132 + r] = q4.z * SCALE_F;
        Qs[(d4+3)*132 + r] = q4.w * SCALE_F;
    }

    float o[8][4];
    float mi[8], li[8];
    #pragma unroll
    for (int i = 0; i < 8; i++) {
        mi[i] = -INFINITY; li[i] = 0.f;
        #pragma unroll
        for (int j = 0; j < 4; j++) o[i][j] = 0.f;
    }

    for (int kt = 0; kt <= qt; kt++) {
        const int k0 = kt * 128;
        __syncthreads();   // previous iteration done reading Ks/Vs/Ps

        // load K (from x) transposed [d][c], and V natural [k][d]
        #pragma unroll
        for (int it = 0; it < 8; it++) {
            const int f = tid + it*256;
            const int r = f >> 4;
            const int d4 = (f & 15) * 4;
            float4 k4 = *reinterpret_cast<const float4*>(xBase + (size_t)(k0 + r)*C_ + d4);
            Ks[(d4+0)*132 + r] = k4.x;
            Ks[(d4+1)*132 + r] = k4.y;
            Ks[(d4+2)*132 + r] = k4.z;
            Ks[(d4+3)*132 + r] = k4.w;
            float4 v4 = *reinterpret_cast<const float4*>(vBase + (size_t)(k0 + r)*HS_ + d4);
            *reinterpret_cast<float4*>(&Vs[r*64 + d4]) = v4;
        }
        __syncthreads();

        // S = Q @ K^T  (already scaled via Q)
        float acc[8][8];
        #pragma unroll
        for (int i = 0; i < 8; i++)
            #pragma unroll
            for (int j = 0; j < 8; j++) acc[i][j] = 0.f;

        #pragma unroll 8
        for (int d = 0; d < 64; d++) {
            float4 a0 = *reinterpret_cast<const float4*>(&Qs[d*132 + ty*8]);
            float4 a1 = *reinterpret_cast<const float4*>(&Qs[d*132 + ty*8 + 4]);
            float4 b0 = *reinterpret_cast<const float4*>(&Ks[d*132 + c0]);
            float4 b1 = *reinterpret_cast<const float4*>(&Ks[d*132 + c0 + 64]);
            float ra[8] = {a0.x,a0.y,a0.z,a0.w,a1.x,a1.y,a1.z,a1.w};
            float rb[8] = {b0.x,b0.y,b0.z,b0.w,b1.x,b1.y,b1.z,b1.w};
            #pragma unroll
            for (int i = 0; i < 8; i++)
                #pragma unroll
                for (int j = 0; j < 8; j++)
                    acc[i][j] = fmaf(ra[i], rb[j], acc[i][j]);
        }

        // causal mask (diagonal tile only; k0 == q0 there)
        if (kt == qt) {
            #pragma unroll
            for (int i = 0; i < 8; i++) {
                const int lq = ty*8 + i;
                #pragma unroll
                for (int j = 0; j < 8; j++) {
                    const int lk = (j < 4) ? (c0 + j) : (64 + c0 + j - 4);
                    if (lk > lq) acc[i][j] = -INFINITY;
                }
            }
        }

        // online softmax (row stats live in registers; 16-lane half-warp reduce)
        #pragma unroll
        for (int i = 0; i < 8; i++) {
            float mx = fmaxf(fmaxf(fmaxf(acc[i][0],acc[i][1]), fmaxf(acc[i][2],acc[i][3])),
                             fmaxf(fmaxf(acc[i][4],acc[i][5]), fmaxf(acc[i][6],acc[i][7])));
            #pragma unroll
            for (int off = 8; off; off >>= 1)
                mx = fmaxf(mx, __shfl_xor_sync(0xffffffffu, mx, off, 16));
            const float mnew = fmaxf(mi[i], mx);
            const float alpha = __expf(mi[i] - mnew);
            mi[i] = mnew;
            float s = 0.f;
            #pragma unroll
            for (int j = 0; j < 8; j++) {
                const float p = __expf(acc[i][j] - mnew);
                acc[i][j] = p;
                s += p;
            }
            #pragma unroll
            for (int off = 8; off; off >>= 1)
                s += __shfl_xor_sync(0xffffffffu, s, off, 16);
            li[i] = li[i]*alpha + s;
            #pragma unroll
            for (int j = 0; j < 4; j++) o[i][j] *= alpha;
        }

        // stage P to smem [r][k]
        #pragma unroll
        for (int i = 0; i < 8; i++) {
            const int r = ty*8 + i;
            *reinterpret_cast<float4*>(&Ps[r*132 + c0]) =
                make_float4(acc[i][0], acc[i][1], acc[i][2], acc[i][3]);
            *reinterpret_cast<float4*>(&Ps[r*132 + c0 + 64]) =
                make_float4(acc[i][4], acc[i][5], acc[i][6], acc[i][7]);
        }
        __syncthreads();

        // O += P @ V
        #pragma unroll 4
        for (int kk = 0; kk < 128; kk += 4) {
            float4 p4[8];
            #pragma unroll
            for (int i = 0; i < 8; i++)
                p4[i] = *reinterpret_cast<const float4*>(&Ps[(ty*8+i)*132 + kk]);
            #pragma unroll
            for (int s = 0; s < 4; s++) {
                float4 v4 = *reinterpret_cast<const float4*>(&Vs[(kk+s)*64 + c0]);
                #pragma unroll
                for (int i = 0; i < 8; i++) {
                    const float pv = (s==0) ? p4[i].x : (s==1) ? p4[i].y :
                                     (s==2) ? p4[i].z : p4[i].w;
                    o[i][0] = fmaf(pv, v4.x, o[i][0]);
                    o[i][1] = fmaf(pv, v4.y, o[i][1]);
                    o[i][2] = fmaf(pv, v4.z, o[i][2]);
                    o[i][3] = fmaf(pv, v4.w, o[i][3]);
                }
            }
        }
    }

    // write y[b, q, h*64 + d]
    float* yBase = g_y + ((size_t)b*T_ + q0)*C_ + h*HS_;
    #pragma unroll
    for (int i = 0; i < 8; i++) {
        const float inv = 1.f / li[i];
        const int r = ty*8 + i;
        float4 w4 = make_float4(o[i][0]*inv, o[i][1]*inv, o[i][2]*inv, o[i][3]*inv);
        *reinterpret_cast<float4*>(&yBase[(size_t)r*C_ + c0]) = w4;
    }
}

// ---------------------------------------------------------------------------
extern "C" void kernel_launch(void* const* d_in, const int* in_sizes, int n_in,
                              void* d_out, int out_size)
{
    (void)in_sizes; (void)n_in; (void)out_size;
    const float* x      = (const float*)d_in[0];
    const float* w_u_w  = (const float*)d_in[1];
    const float* w_u_b  = (const float*)d_in[2];
    const float* w_v_w  = (const float*)d_in[3];
    const float* w_v_b  = (const float*)d_in[4];
    const float* proj_w = (const float*)d_in[5];
    const float* proj_b = (const float*)d_in[6];
    float* out = (float*)d_out;

    cudaFuncSetAttribute(attn_kernel,
                         cudaFuncAttributeMaxDynamicSharedMemorySize,
                         ATTN_SMEM_BYTES);

    dim3 ggrid(C_/128, M_TOT/64);   // (6, 64)
    gemm_xwT_kernel<0><<<ggrid, 256>>>(x, w_u_w, w_u_b, nullptr);   // u
    gemm_xwT_kernel<1><<<ggrid, 256>>>(x, w_v_w, w_v_b, nullptr);   // v
    attn_kernel<<<dim3(T_/128, B_*H_), 256, ATTN_SMEM_BYTES>>>(x);  // y
    gemm_xwT_kernel<2><<<ggrid, 256>>>(nullptr, proj_w, proj_b, out); // out
}

// round 3
// speedup vs baseline: 1.3908x; 1.3908x over previous
#include <cuda_runtime.h>
#include <cuda_bf16.h>
#include <math.h>
#include <stdint.h>

#define B_   2
#define T_   2048
#define C_   768
#define H_   12
#define HS_  64
#define M_TOT (B_*T_)            // 4096
#define SCALE_F 0.03608439182435161f   // 1/sqrt(768)

// ---------------- scratch (device globals; no allocations allowed) ----------
__device__ float g_u[B_*H_*T_*HS_];   // queries, [b,h,t,hs]
__device__ float g_v[B_*H_*T_*HS_];   // values,  [b,h,t,hs]
__device__ float g_y[B_*T_*C_];       // attn output, [b,t,c]

__device__ __nv_bfloat16 g_xhi[M_TOT*C_], g_xlo[M_TOT*C_];
__device__ __nv_bfloat16 g_yhi[M_TOT*C_], g_ylo[M_TOT*C_];
__device__ __nv_bfloat16 g_wuhi[C_*C_], g_wulo[C_*C_];
__device__ __nv_bfloat16 g_wvhi[C_*C_], g_wvlo[C_*C_];
__device__ __nv_bfloat16 g_wphi[C_*C_], g_wplo[C_*C_];

// ---------------------------------------------------------------------------
__device__ __forceinline__ uint32_t smem_u32(const void* p) {
    uint32_t a;
    asm("{ .reg .u64 t; cvta.to.shared.u64 t, %1; cvt.u32.u64 %0, t; }"
        : "=r"(a) : "l"(p));
    return a;
}
__device__ __forceinline__ void ldsm_x4(uint32_t (&r)[4], uint32_t addr) {
    asm volatile("ldmatrix.sync.aligned.m8n8.x4.shared.b16 {%0,%1,%2,%3}, [%4];"
        : "=r"(r[0]), "=r"(r[1]), "=r"(r[2]), "=r"(r[3]) : "r"(addr));
}
__device__ __forceinline__ void mma16816(float (&d)[4], const uint32_t (&a)[4],
                                         uint32_t b0, uint32_t b1) {
    asm volatile(
        "mma.sync.aligned.m16n8k16.row.col.f32.bf16.bf16.f32 "
        "{%0,%1,%2,%3}, {%4,%5,%6,%7}, {%8,%9}, {%0,%1,%2,%3};"
        : "+f"(d[0]), "+f"(d[1]), "+f"(d[2]), "+f"(d[3])
        : "r"(a[0]), "r"(a[1]), "r"(a[2]), "r"(a[3]), "r"(b0), "r"(b1));
}

// ---------------------------------------------------------------------------
// fp32 -> bf16 hi/lo split.  SRC: 0=x(arg) 1..3=w(arg) 4=g_y
// ---------------------------------------------------------------------------
template<int SRC>
__global__ void split_kernel(const float* __restrict__ in, int n4)
{
    int i = blockIdx.x * blockDim.x + threadIdx.x;
    if (i >= n4) return;
    const float* src = (SRC == 4) ? (const float*)g_y : in;
    __nv_bfloat16* hi = (SRC == 0) ? g_xhi : (SRC == 1) ? g_wuhi :
                        (SRC == 2) ? g_wvhi : (SRC == 3) ? g_wphi : g_yhi;
    __nv_bfloat16* lo = (SRC == 0) ? g_xlo : (SRC == 1) ? g_wulo :
                        (SRC == 2) ? g_wvlo : (SRC == 3) ? g_wplo : g_ylo;
    float4 v = reinterpret_cast<const float4*>(src)[i];
    float vs[4] = {v.x, v.y, v.z, v.w};
    __nv_bfloat16 h[4], l[4];
    #pragma unroll
    for (int j = 0; j < 4; j++) {
        h[j] = __float2bfloat16(vs[j]);
        l[j] = __float2bfloat16(vs[j] - __bfloat162float(h[j]));
    }
    reinterpret_cast<__nv_bfloat162*>(hi)[i*2+0] = __halves2bfloat162(h[0], h[1]);
    reinterpret_cast<__nv_bfloat162*>(hi)[i*2+1] = __halves2bfloat162(h[2], h[3]);
    reinterpret_cast<__nv_bfloat162*>(lo)[i*2+0] = __halves2bfloat162(l[0], l[1]);
    reinterpret_cast<__nv_bfloat162*>(lo)[i*2+1] = __halves2bfloat162(l[2], l[3]);
}

// ---------------------------------------------------------------------------
// HMMA GEMM: D[m,n] = sum_k A[m,k]*W[n,k] + bias[n]
// split bf16: D = Ahi*Bhi + Ahi*Blo + Alo*Bhi (fp32 accum in registers)
// CTA tile 128x128, 8 warps (warp tile 64x32), K chunks of 64 in smem.
// smem layout (per chunk): Ahi@0 Alo@16K Bhi@32K Blo@48K, rows of 64 bf16
// (128B) with 16B-granular XOR swizzle: chunk' = chunk ^ (row&7).
// MODE 0: A=x,B=w_u -> g_u;  MODE 1: A=x,B=w_v -> g_v;  MODE 2: A=y,B=proj -> outp
// ---------------------------------------------------------------------------
#define GEMM_SMEM_BYTES 65536

template<int MODE>
__global__ __launch_bounds__(256, 2)
void gemm_mma(const float* __restrict__ bias, float* __restrict__ outp)
{
    extern __shared__ char sm[];
    const uint32_t sb = smem_u32(sm);

    const __nv_bfloat16* Ahi = (MODE == 2) ? g_yhi : g_xhi;
    const __nv_bfloat16* Alo = (MODE == 2) ? g_ylo : g_xlo;
    const __nv_bfloat16* Bhi = (MODE == 0) ? g_wuhi : (MODE == 1) ? g_wvhi : g_wphi;
    const __nv_bfloat16* Blo = (MODE == 0) ? g_wulo : (MODE == 1) ? g_wvlo : g_wplo;

    const int tid = threadIdx.x;
    const int wid = tid >> 5, lane = tid & 31;
    const int m0 = blockIdx.y * 128;
    const int n0 = blockIdx.x * 128;
    const int wm = (wid & 1) * 64;       // warp M offset in tile
    const int wn = (wid >> 1) * 32;      // warp N offset in tile

    float acc[4][4][4];
    #pragma unroll
    for (int a = 0; a < 4; a++)
        #pragma unroll
        for (int b = 0; b < 4; b++)
            #pragma unroll
            for (int c = 0; c < 4; c++) acc[a][b][c] = 0.f;

    // global-load mapping: flat chunk f in [0,1024): row=f>>3, ch=f&7 (16B chunks)
    // smem addr = row*128 + ((ch ^ (row&7))<<4)
    int ldrow[4], ldswo[4];
    #pragma unroll
    for (int it = 0; it < 4; it++) {
        int f = tid + it * 256;
        int r = f >> 3, ch = f & 7;
        ldrow[it] = r;
        ldswo[it] = r * 128 + ((ch ^ (r & 7)) << 4);
    }

    // ldmatrix lane bases
    const int a_r = (lane & 15);               // + wm + mt*16
    const int a_co = (lane >> 4);              // chunk offset 0/1
    const int b_r = (lane & 7) + ((lane >> 4) << 3);  // + wn + bt*16
    const int b_co = (lane >> 3) & 1;

    for (int kc = 0; kc < 12; kc++) {
        __syncthreads();   // previous iteration done reading smem
        const int kcol = kc * 64;
        #pragma unroll
        for (int it = 0; it < 4; it++) {
            const int f = tid + it * 256;
            const int ch = f & 7;
            const size_t ga = (size_t)(m0 + ldrow[it]) * C_ + kcol + ch * 8;
            const size_t gb = (size_t)(n0 + ldrow[it]) * C_ + kcol + ch * 8;
            *(uint4*)(sm + ldswo[it] + 0)     = *(const uint4*)(Ahi + ga);
            *(uint4*)(sm + ldswo[it] + 16384) = *(const uint4*)(Alo + ga);
            *(uint4*)(sm + ldswo[it] + 32768) = *(const uint4*)(Bhi + gb);
            *(uint4*)(sm + ldswo[it] + 49152) = *(const uint4*)(Blo + gb);
        }
        __syncthreads();

        #pragma unroll
        for (int ks = 0; ks < 4; ks++) {
            const int kb = ks * 2;   // 16B-chunk base of this k16 step
            uint32_t bhi[2][4], blo[2][4];
            #pragma unroll
            for (int bt = 0; bt < 2; bt++) {
                const int row = wn + bt * 16 + b_r;
                const uint32_t ad = sb + 32768 + row * 128 +
                                    (((kb + b_co) ^ (row & 7)) << 4);
                ldsm_x4(bhi[bt], ad);
                ldsm_x4(blo[bt], ad + 16384);
            }
            #pragma unroll
            for (int mt = 0; mt < 4; mt++) {
                const int row = wm + mt * 16 + a_r;
                const uint32_t ad = sb + row * 128 +
                                    (((kb + a_co) ^ (row & 7)) << 4);
                uint32_t ahi[4], alo[4];
                ldsm_x4(ahi, ad);
                ldsm_x4(alo, ad + 16384);
                #pragma unroll
                for (int nt = 0; nt < 4; nt++) {
                    const int bt = nt >> 1, hf = (nt & 1) * 2;
                    mma16816(acc[mt][nt], ahi, bhi[bt][hf], bhi[bt][hf + 1]);
                    mma16816(acc[mt][nt], ahi, blo[bt][hf], blo[bt][hf + 1]);
                    mma16816(acc[mt][nt], alo, bhi[bt][hf], bhi[bt][hf + 1]);
                }
            }
        }
    }

    // epilogue: d-frag layout: rows lane/4 and lane/4+8; cols 2*(lane%4), +1
    const int er = lane >> 2, ec = (lane & 3) * 2;
    #pragma unroll
    for (int mt = 0; mt < 4; mt++) {
        #pragma unroll
        for (int nt = 0; nt < 4; nt++) {
            const int n = n0 + wn + nt * 8 + ec;
            const float b0 = bias[n], b1 = bias[n + 1];
            #pragma unroll
            for (int half = 0; half < 2; half++) {
                const int m = m0 + wm + mt * 16 + er + half * 8;
                const float v0 = acc[mt][nt][half * 2 + 0] + b0;
                const float v1 = acc[mt][nt][half * 2 + 1] + b1;
                if (MODE == 2) {
                    *(float2*)(outp + (size_t)m * C_ + n) = make_float2(v0, v1);
                } else {
                    const int bb = m >> 11, t = m & (T_ - 1);
                    const int h = n >> 6, hs = n & 63;
                    float* dst = (MODE == 0) ? g_u : g_v;
                    *(float2*)(dst + (((size_t)(bb * H_ + h)) * T_ + t) * HS_ + hs) =
                        make_float2(v0, v1);
                }
            }
        }
    }
}

// ---------------------------------------------------------------------------
// Flash attention, fp32 (unchanged — passes at rel_err 7.6e-7)
// ---------------------------------------------------------------------------
#define ATTN_SMEM_FLOATS (64*132 + 64*132 + 128*64 + 128*132)
#define ATTN_SMEM_BYTES  (ATTN_SMEM_FLOATS * 4)

__global__ __launch_bounds__(256, 1)
void attn_kernel(const float* __restrict__ x)
{
    extern __shared__ float smem[];
    float* Qs = smem;
    float* Ks = Qs + 64*132;
    float* Vs = Ks + 64*132;
    float* Ps = Vs + 128*64;

    const int tid = threadIdx.x;
    const int tx = tid & 15, ty = tid >> 4;
    const int c0 = tx * 4;

    const int qt = (int)(gridDim.x - 1) - (int)blockIdx.x;
    const int bh = blockIdx.y;
    const int b = bh / H_, h = bh % H_;
    const int q0 = qt * 128;

    const float* uBase = g_u + (size_t)bh * T_ * HS_;
    const float* vBase = g_v + (size_t)bh * T_ * HS_;
    const float* xBase = x + (size_t)b * T_ * C_ + h * HS_;

    #pragma unroll
    for (int it = 0; it < 8; it++) {
        const int f = tid + it*256;
        const int r = f >> 4;
        const int d4 = (f & 15) * 4;
        float4 q4 = *reinterpret_cast<const float4*>(uBase + (size_t)(q0 + r)*HS_ + d4);
        Qs[(d4+0)*132 + r] = q4.x * SCALE_F;
        Qs[(d4+1)*132 + r] = q4.y * SCALE_F;
        Qs[(d4+2)*132 + r] = q4.z * SCALE_F;
        Qs[(d4+3)*132 + r] = q4.w * SCALE_F;
    }

    float o[8][4];
    float mi[8], li[8];
    #pragma unroll
    for (int i = 0; i < 8; i++) {
        mi[i] = -INFINITY; li[i] = 0.f;
        #pragma unroll
        for (int j = 0; j < 4; j++) o[i][j] = 0.f;
    }

    for (int kt = 0; kt <= qt; kt++) {
        const int k0 = kt * 128;
        __syncthreads();

        #pragma unroll
        for (int it = 0; it < 8; it++) {
            const int f = tid + it*256;
            const int r = f >> 4;
            const int d4 = (f & 15) * 4;
            float4 k4 = *reinterpret_cast<const float4*>(xBase + (size_t)(k0 + r)*C_ + d4);
            Ks[(d4+0)*132 + r] = k4.x;
            Ks[(d4+1)*132 + r] = k4.y;
            Ks[(d4+2)*132 + r] = k4.z;
            Ks[(d4+3)*132 + r] = k4.w;
            float4 v4 = *reinterpret_cast<const float4*>(vBase + (size_t)(k0 + r)*HS_ + d4);
            *reinterpret_cast<float4*>(&Vs[r*64 + d4]) = v4;
        }
        __syncthreads();

        float acc[8][8];
        #pragma unroll
        for (int i = 0; i < 8; i++)
            #pragma unroll
            for (int j = 0; j < 8; j++) acc[i][j] = 0.f;

        #pragma unroll 8
        for (int d = 0; d < 64; d++) {
            float4 a0 = *reinterpret_cast<const float4*>(&Qs[d*132 + ty*8]);
            float4 a1 = *reinterpret_cast<const float4*>(&Qs[d*132 + ty*8 + 4]);
            float4 b0 = *reinterpret_cast<const float4*>(&Ks[d*132 + c0]);
            float4 b1 = *reinterpret_cast<const float4*>(&Ks[d*132 + c0 + 64]);
            float ra[8] = {a0.x,a0.y,a0.z,a0.w,a1.x,a1.y,a1.z,a1.w};
            float rb[8] = {b0.x,b0.y,b0.z,b0.w,b1.x,b1.y,b1.z,b1.w};
            #pragma unroll
            for (int i = 0; i < 8; i++)
                #pragma unroll
                for (int j = 0; j < 8; j++)
                    acc[i][j] = fmaf(ra[i], rb[j], acc[i][j]);
        }

        if (kt == qt) {
            #pragma unroll
            for (int i = 0; i < 8; i++) {
                const int lq = ty*8 + i;
                #pragma unroll
                for (int j = 0; j < 8; j++) {
                    const int lk = (j < 4) ? (c0 + j) : (64 + c0 + j - 4);
                    if (lk > lq) acc[i][j] = -INFINITY;
                }
            }
        }

        #pragma unroll
        for (int i = 0; i < 8; i++) {
            float mx = fmaxf(fmaxf(fmaxf(acc[i][0],acc[i][1]), fmaxf(acc[i][2],acc[i][3])),
                             fmaxf(fmaxf(acc[i][4],acc[i][5]), fmaxf(acc[i][6],acc[i][7])));
            #pragma unroll
            for (int off = 8; off; off >>= 1)
                mx = fmaxf(mx, __shfl_xor_sync(0xffffffffu, mx, off, 16));
            const float mnew = fmaxf(mi[i], mx);
            const float alpha = __expf(mi[i] - mnew);
            mi[i] = mnew;
            float s = 0.f;
            #pragma unroll
            for (int j = 0; j < 8; j++) {
                const float p = __expf(acc[i][j] - mnew);
                acc[i][j] = p;
                s += p;
            }
            #pragma unroll
            for (int off = 8; off; off >>= 1)
                s += __shfl_xor_sync(0xffffffffu, s, off, 16);
            li[i] = li[i]*alpha + s;
            #pragma unroll
            for (int j = 0; j < 4; j++) o[i][j] *= alpha;
        }

        #pragma unroll
        for (int i = 0; i < 8; i++) {
            const int r = ty*8 + i;
            *reinterpret_cast<float4*>(&Ps[r*132 + c0]) =
                make_float4(acc[i][0], acc[i][1], acc[i][2], acc[i][3]);
            *reinterpret_cast<float4*>(&Ps[r*132 + c0 + 64]) =
                make_float4(acc[i][4], acc[i][5], acc[i][6], acc[i][7]);
        }
        __syncthreads();

        #pragma unroll 4
        for (int kk = 0; kk < 128; kk += 4) {
            float4 p4[8];
            #pragma unroll
            for (int i = 0; i < 8; i++)
                p4[i] = *reinterpret_cast<const float4*>(&Ps[(ty*8+i)*132 + kk]);
            #pragma unroll
            for (int s = 0; s < 4; s++) {
                float4 v4 = *reinterpret_cast<const float4*>(&Vs[(kk+s)*64 + c0]);
                #pragma unroll
                for (int i = 0; i < 8; i++) {
                    const float pv = (s==0) ? p4[i].x : (s==1) ? p4[i].y :
                                     (s==2) ? p4[i].z : p4[i].w;
                    o[i][0] = fmaf(pv, v4.x, o[i][0]);
                    o[i][1] = fmaf(pv, v4.y, o[i][1]);
                    o[i][2] = fmaf(pv, v4.z, o[i][2]);
                    o[i][3] = fmaf(pv, v4.w, o[i][3]);
                }
            }
        }
    }

    float* yBase = g_y + ((size_t)b*T_ + q0)*C_ + h*HS_;
    #pragma unroll
    for (int i = 0; i < 8; i++) {
        const float inv = 1.f / li[i];
        const int r = ty*8 + i;
        float4 w4 = make_float4(o[i][0]*inv, o[i][1]*inv, o[i][2]*inv, o[i][3]*inv);
        *reinterpret_cast<float4*>(&yBase[(size_t)r*C_ + c0]) = w4;
    }
}

// ---------------------------------------------------------------------------
extern "C" void kernel_launch(void* const* d_in, const int* in_sizes, int n_in,
                              void* d_out, int out_size)
{
    (void)in_sizes; (void)n_in; (void)out_size;
    const float* x      = (const float*)d_in[0];
    const float* w_u_b  = (const float*)d_in[2];
    const float* w_v_b  = (const float*)d_in[4];
    const float* proj_b = (const float*)d_in[6];
    float* out = (float*)d_out;

    cudaFuncSetAttribute(attn_kernel,
                         cudaFuncAttributeMaxDynamicSharedMemorySize, ATTN_SMEM_BYTES);
    cudaFuncSetAttribute(gemm_mma<0>,
                         cudaFuncAttributeMaxDynamicSharedMemorySize, GEMM_SMEM_BYTES);
    cudaFuncSetAttribute(gemm_mma<1>,
                         cudaFuncAttributeMaxDynamicSharedMemorySize, GEMM_SMEM_BYTES);
    cudaFuncSetAttribute(gemm_mma<2>,
                         cudaFuncAttributeMaxDynamicSharedMemorySize, GEMM_SMEM_BYTES);

    const int n4x = (M_TOT * C_) / 4;   // 786432
    const int n4w = (C_ * C_) / 4;      // 147456

    split_kernel<0><<<(n4x + 255) / 256, 256>>>(x, n4x);
    split_kernel<1><<<(n4w + 255) / 256, 256>>>((const float*)d_in[1], n4w);
    split_kernel<2><<<(n4w + 255) / 256, 256>>>((const float*)d_in[3], n4w);
    split_kernel<3><<<(n4w + 255) / 256, 256>>>((const float*)d_in[5], n4w);

    dim3 ggrid(C_ / 128, M_TOT / 128);   // (6, 32)
    gemm_mma<0><<<ggrid, 256, GEMM_SMEM_BYTES>>>(w_u_b, nullptr);   // u
    gemm_mma<1><<<ggrid, 256, GEMM_SMEM_BYTES>>>(w_v_b, nullptr);   // v

    attn_kernel<<<dim3(T_/128, B_*H_), 256, ATTN_SMEM_BYTES>>>(x);  // y -> g_y

    split_kernel<4><<<(n4x + 255) / 256, 256>>>(nullptr, n4x);      // y -> hi/lo
    gemm_mma<2><<<ggrid, 256, GEMM_SMEM_BYTES>>>(proj_b, out);      // out
}

// round 4
// speedup vs baseline: 2.4210x; 1.7407x over previous
#include <cuda_runtime.h>
#include <cuda_bf16.h>
#include <math.h>
#include <stdint.h>

#define B_   2
#define T_   2048
#define C_   768
#define H_   12
#define HS_  64
#define M_TOT (B_*T_)            // 4096
#define SCALE_F 0.03608439182435161f   // 1/sqrt(768)

// ---------------- scratch (device globals; no allocations allowed) ----------
__device__ __nv_bfloat16 g_xhi[M_TOT*C_], g_xlo[M_TOT*C_];
__device__ __nv_bfloat16 g_yhi[M_TOT*C_], g_ylo[M_TOT*C_];
__device__ __nv_bfloat16 g_uhi[M_TOT*C_], g_ulo[M_TOT*C_];  // scaled Q, [b,h,t,hs]
__device__ __nv_bfloat16 g_vhi[M_TOT*C_], g_vlo[M_TOT*C_];  // V, [b,h,t,hs]
__device__ __nv_bfloat16 g_wuhi[C_*C_], g_wulo[C_*C_];
__device__ __nv_bfloat16 g_wvhi[C_*C_], g_wvlo[C_*C_];
__device__ __nv_bfloat16 g_wphi[C_*C_], g_wplo[C_*C_];

// ---------------------------------------------------------------------------
__device__ __forceinline__ uint32_t smem_u32(const void* p) {
    uint32_t a;
    asm("{ .reg .u64 t; cvta.to.shared.u64 t, %1; cvt.u32.u64 %0, t; }"
        : "=r"(a) : "l"(p));
    return a;
}
__device__ __forceinline__ void ldsm_x4(uint32_t (&r)[4], uint32_t addr) {
    asm volatile("ldmatrix.sync.aligned.m8n8.x4.shared.b16 {%0,%1,%2,%3}, [%4];"
        : "=r"(r[0]), "=r"(r[1]), "=r"(r[2]), "=r"(r[3]) : "r"(addr));
}
__device__ __forceinline__ void ldsm_x2t(uint32_t (&r)[2], uint32_t addr) {
    asm volatile("ldmatrix.sync.aligned.m8n8.x2.trans.shared.b16 {%0,%1}, [%2];"
        : "=r"(r[0]), "=r"(r[1]) : "r"(addr));
}
__device__ __forceinline__ void mma16816(float (&d)[4], const uint32_t (&a)[4],
                                         uint32_t b0, uint32_t b1) {
    asm volatile(
        "mma.sync.aligned.m16n8k16.row.col.f32.bf16.bf16.f32 "
        "{%0,%1,%2,%3}, {%4,%5,%6,%7}, {%8,%9}, {%0,%1,%2,%3};"
        : "+f"(d[0]), "+f"(d[1]), "+f"(d[2]), "+f"(d[3])
        : "r"(a[0]), "r"(a[1]), "r"(a[2]), "r"(a[3]), "r"(b0), "r"(b1));
}
// split two fp32 into packed bf16 hi / lo pairs
__device__ __forceinline__ void split2(float f0, float f1, uint32_t& hi, uint32_t& lo) {
    __nv_bfloat16 h0 = __float2bfloat16(f0), h1 = __float2bfloat16(f1);
    __nv_bfloat16 l0 = __float2bfloat16(f0 - __bfloat162float(h0));
    __nv_bfloat16 l1 = __float2bfloat16(f1 - __bfloat162float(h1));
    __nv_bfloat162 Hp = __halves2bfloat162(h0, h1), Lp = __halves2bfloat162(l0, l1);
    hi = *(uint32_t*)&Hp; lo = *(uint32_t*)&Lp;
}

// ---------------------------------------------------------------------------
// fp32 -> bf16 hi/lo split.  SRC: 0=x 1=w_u 2=w_v 3=w_p
// ---------------------------------------------------------------------------
template<int SRC>
__global__ void split_kernel(const float* __restrict__ in, int n4)
{
    int i = blockIdx.x * blockDim.x + threadIdx.x;
    if (i >= n4) return;
    __nv_bfloat16* hi = (SRC == 0) ? g_xhi : (SRC == 1) ? g_wuhi :
                        (SRC == 2) ? g_wvhi : g_wphi;
    __nv_bfloat16* lo = (SRC == 0) ? g_xlo : (SRC == 1) ? g_wulo :
                        (SRC == 2) ? g_wvlo : g_wplo;
    float4 v = reinterpret_cast<const float4*>(in)[i];
    uint32_t h0, l0, h1, l1;
    split2(v.x, v.y, h0, l0);
    split2(v.z, v.w, h1, l1);
    reinterpret_cast<uint32_t*>(hi)[i*2+0] = h0;
    reinterpret_cast<uint32_t*>(hi)[i*2+1] = h1;
    reinterpret_cast<uint32_t*>(lo)[i*2+0] = l0;
    reinterpret_cast<uint32_t*>(lo)[i*2+1] = l1;
}

// ---------------------------------------------------------------------------
// HMMA GEMM: D[m,n] = sum_k A[m,k]*W[n,k] + bias[n]  (split bf16, 3 MMAs)
// CTA 128x128, 8 warps (64x32 warp tile), K chunks of 64 in smem.
// MODE 0: x@w_u -> g_uhi/ulo scaled by SCALE_F, [b,h,t,hs]
// MODE 1: x@w_v -> g_vhi/vlo, [b,h,t,hs]
// MODE 2: y@proj -> outp fp32
// ---------------------------------------------------------------------------
#define GEMM_SMEM_BYTES 65536

template<int MODE>
__global__ __launch_bounds__(256, 2)
void gemm_mma(const float* __restrict__ bias, float* __restrict__ outp)
{
    extern __shared__ char sm[];
    const uint32_t sb = smem_u32(sm);

    const __nv_bfloat16* Ahi = (MODE == 2) ? g_yhi : g_xhi;
    const __nv_bfloat16* Alo = (MODE == 2) ? g_ylo : g_xlo;
    const __nv_bfloat16* Bhi = (MODE == 0) ? g_wuhi : (MODE == 1) ? g_wvhi : g_wphi;
    const __nv_bfloat16* Blo = (MODE == 0) ? g_wulo : (MODE == 1) ? g_wvlo : g_wplo;

    const int tid = threadIdx.x;
    const int wid = tid >> 5, lane = tid & 31;
    const int m0 = blockIdx.y * 128;
    const int n0 = blockIdx.x * 128;
    const int wm = (wid & 1) * 64;
    const int wn = (wid >> 1) * 32;

    float acc[4][4][4];
    #pragma unroll
    for (int a = 0; a < 4; a++)
        #pragma unroll
        for (int b = 0; b < 4; b++)
            #pragma unroll
            for (int c = 0; c < 4; c++) acc[a][b][c] = 0.f;

    int ldrow[4], ldswo[4];
    #pragma unroll
    for (int it = 0; it < 4; it++) {
        int f = tid + it * 256;
        int r = f >> 3, ch = f & 7;
        ldrow[it] = r;
        ldswo[it] = r * 128 + ((ch ^ (r & 7)) << 4);
    }

    const int a_r = (lane & 15);
    const int a_co = (lane >> 4);
    const int b_r = (lane & 7) + ((lane >> 4) << 3);
    const int b_co = (lane >> 3) & 1;

    for (int kc = 0; kc < 12; kc++) {
        __syncthreads();
        const int kcol = kc * 64;
        #pragma unroll
        for (int it = 0; it < 4; it++) {
            const int f = tid + it * 256;
            const int ch = f & 7;
            const size_t ga = (size_t)(m0 + ldrow[it]) * C_ + kcol + ch * 8;
            const size_t gb = (size_t)(n0 + ldrow[it]) * C_ + kcol + ch * 8;
            *(uint4*)(sm + ldswo[it] + 0)     = *(const uint4*)(Ahi + ga);
            *(uint4*)(sm + ldswo[it] + 16384) = *(const uint4*)(Alo + ga);
            *(uint4*)(sm + ldswo[it] + 32768) = *(const uint4*)(Bhi + gb);
            *(uint4*)(sm + ldswo[it] + 49152) = *(const uint4*)(Blo + gb);
        }
        __syncthreads();

        #pragma unroll
        for (int ks = 0; ks < 4; ks++) {
            const int kb = ks * 2;
            uint32_t bhi[2][4], blo[2][4];
            #pragma unroll
            for (int bt = 0; bt < 2; bt++) {
                const int row = wn + bt * 16 + b_r;
                const uint32_t ad = sb + 32768 + row * 128 +
                                    (((kb + b_co) ^ (row & 7)) << 4);
                ldsm_x4(bhi[bt], ad);
                ldsm_x4(blo[bt], ad + 16384);
            }
            #pragma unroll
            for (int mt = 0; mt < 4; mt++) {
                const int row = wm + mt * 16 + a_r;
                const uint32_t ad = sb + row * 128 +
                                    (((kb + a_co) ^ (row & 7)) << 4);
                uint32_t ahi[4], alo[4];
                ldsm_x4(ahi, ad);
                ldsm_x4(alo, ad + 16384);
                #pragma unroll
                for (int nt = 0; nt < 4; nt++) {
                    const int bt = nt >> 1, hf = (nt & 1) * 2;
                    mma16816(acc[mt][nt], ahi, bhi[bt][hf], bhi[bt][hf + 1]);
                    mma16816(acc[mt][nt], ahi, blo[bt][hf], blo[bt][hf + 1]);
                    mma16816(acc[mt][nt], alo, bhi[bt][hf], bhi[bt][hf + 1]);
                }
            }
        }
    }

    const int er = lane >> 2, ec = (lane & 3) * 2;
    #pragma unroll
    for (int mt = 0; mt < 4; mt++) {
        #pragma unroll
        for (int nt = 0; nt < 4; nt++) {
            const int n = n0 + wn + nt * 8 + ec;
            const float b0 = bias[n], b1 = bias[n + 1];
            #pragma unroll
            for (int half = 0; half < 2; half++) {
                const int m = m0 + wm + mt * 16 + er + half * 8;
                float v0 = acc[mt][nt][half * 2 + 0] + b0;
                float v1 = acc[mt][nt][half * 2 + 1] + b1;
                if (MODE == 2) {
                    *(float2*)(outp + (size_t)m * C_ + n) = make_float2(v0, v1);
                } else {
                    if (MODE == 0) { v0 *= SCALE_F; v1 *= SCALE_F; }
                    const int bb = m >> 11, t = m & (T_ - 1);
                    const int hh = n >> 6, hs = n & 63;
                    uint32_t hi, lo;
                    split2(v0, v1, hi, lo);
                    __nv_bfloat16* dhi = (MODE == 0) ? g_uhi : g_vhi;
                    __nv_bfloat16* dlo = (MODE == 0) ? g_ulo : g_vlo;
                    const size_t off = (((size_t)(bb * H_ + hh)) * T_ + t) * HS_ + hs;
                    *(uint32_t*)(dhi + off) = hi;
                    *(uint32_t*)(dlo + off) = lo;
                }
            }
        }
    }
}

// ---------------------------------------------------------------------------
// HMMA flash attention, split bf16 on both matmuls.
// CTA: 128 q-rows, 8 warps (16 rows each, full 128 kv cols). KV tile 128.
// smem: Qhi@0 Qlo@16K Khi@32K Klo@48K Vhi@64K Vlo@80K  (96KB)
// Q pre-scaled. K = raw x head slice. Writes y as bf16 hi/lo.
// ---------------------------------------------------------------------------
#define ATTN_SMEM 98304

__global__ __launch_bounds__(256, 1)
void attn_mma()
{
    extern __shared__ char sm[];
    const uint32_t sb = smem_u32(sm);
    const int tid = threadIdx.x, wid = tid >> 5, lane = tid & 31;
    const int qt = (int)(gridDim.x - 1) - (int)blockIdx.x;  // longest first
    const int bh = blockIdx.y;
    const int b = bh / H_, h = bh % H_;
    const int q0 = qt * 128;

    const __nv_bfloat16* Kh = g_xhi + (size_t)b * T_ * C_ + h * HS_;
    const __nv_bfloat16* Kl = g_xlo + (size_t)b * T_ * C_ + h * HS_;
    const __nv_bfloat16* Vh = g_vhi + (size_t)bh * T_ * HS_;
    const __nv_bfloat16* Vl = g_vlo + (size_t)bh * T_ * HS_;
    const __nv_bfloat16* Qh = g_uhi + (size_t)bh * T_ * HS_;
    const __nv_bfloat16* Ql = g_ulo + (size_t)bh * T_ * HS_;

    int ldr[4], ldo[4];
    #pragma unroll
    for (int it = 0; it < 4; it++) {
        int f = tid + it * 256;
        int r = f >> 3, ch = f & 7;
        ldr[it] = r;
        ldo[it] = r * 128 + ((ch ^ (r & 7)) << 4);
    }
    // stage Q tile (hi/lo)
    #pragma unroll
    for (int it = 0; it < 4; it++) {
        int f = tid + it * 256;
        int ch = f & 7;
        size_t g = (size_t)(q0 + ldr[it]) * HS_ + ch * 8;
        *(uint4*)(sm + ldo[it])         = *(const uint4*)(Qh + g);
        *(uint4*)(sm + 16384 + ldo[it]) = *(const uint4*)(Ql + g);
    }

    const int a_r = lane & 15, a_co = lane >> 4;
    const int b_r = (lane & 7) + ((lane >> 4) << 3), b_co = (lane >> 3) & 1;

    float onn[8][4];
    #pragma unroll
    for (int i = 0; i < 8; i++)
        #pragma unroll
        for (int j = 0; j < 4; j++) onn[i][j] = 0.f;
    float mi0 = -INFINITY, mi1 = -INFINITY, li0 = 0.f, li1 = 0.f;

    for (int kt = 0; kt <= qt; kt++) {
        const int k0 = kt * 128;
        __syncthreads();   // previous iteration done reading K/V smem
        #pragma unroll
        for (int it = 0; it < 4; it++) {
            int f = tid + it * 256;
            int ch = f & 7;
            size_t gk = (size_t)(k0 + ldr[it]) * C_ + ch * 8;
            size_t gv = (size_t)(k0 + ldr[it]) * HS_ + ch * 8;
            *(uint4*)(sm + 32768 + ldo[it]) = *(const uint4*)(Kh + gk);
            *(uint4*)(sm + 49152 + ldo[it]) = *(const uint4*)(Kl + gk);
            *(uint4*)(sm + 65536 + ldo[it]) = *(const uint4*)(Vh + gv);
            *(uint4*)(sm + 81920 + ldo[it]) = *(const uint4*)(Vl + gv);
        }
        __syncthreads();

        // ---- S = Q @ K^T (split, fp32 acc) ----
        float s[16][4];
        #pragma unroll
        for (int i = 0; i < 16; i++)
            #pragma unroll
            for (int j = 0; j < 4; j++) s[i][j] = 0.f;

        #pragma unroll
        for (int ks = 0; ks < 4; ks++) {
            uint32_t qh[4], ql[4];
            {
                const int row = wid * 16 + a_r;
                const uint32_t ad = sb + row * 128 +
                                    (((ks * 2 + a_co) ^ (row & 7)) << 4);
                ldsm_x4(qh, ad);
                ldsm_x4(ql, ad + 16384);
            }
            #pragma unroll
            for (int bt = 0; bt < 8; bt++) {
                const int row = bt * 16 + b_r;
                const uint32_t ad = sb + 32768 + row * 128 +
                                    (((ks * 2 + b_co) ^ (row & 7)) << 4);
                uint32_t kh[4], kl[4];
                ldsm_x4(kh, ad);
                ldsm_x4(kl, ad + 16384);
                #pragma unroll
                for (int hf = 0; hf < 2; hf++) {
                    const int nt = bt * 2 + hf;
                    mma16816(s[nt], qh, kh[hf*2], kh[hf*2+1]);
                    mma16816(s[nt], qh, kl[hf*2], kl[hf*2+1]);
                    mma16816(s[nt], ql, kh[hf*2], kh[hf*2+1]);
                }
            }
        }

        // ---- causal mask (diagonal tile only; k0 == q0) ----
        if (kt == qt) {
            const int r0 = wid * 16 + (lane >> 2);
            #pragma unroll
            for (int nt = 0; nt < 16; nt++) {
                const int c = nt * 8 + 2 * (lane & 3);
                if (c     > r0)     s[nt][0] = -INFINITY;
                if (c + 1 > r0)     s[nt][1] = -INFINITY;
                if (c     > r0 + 8) s[nt][2] = -INFINITY;
                if (c + 1 > r0 + 8) s[nt][3] = -INFINITY;
            }
        }

        // ---- online softmax (rows r0, r0+8 per thread-quad) ----
        float mx0 = -INFINITY, mx1 = -INFINITY;
        #pragma unroll
        for (int nt = 0; nt < 16; nt++) {
            mx0 = fmaxf(mx0, fmaxf(s[nt][0], s[nt][1]));
            mx1 = fmaxf(mx1, fmaxf(s[nt][2], s[nt][3]));
        }
        mx0 = fmaxf(mx0, __shfl_xor_sync(0xffffffffu, mx0, 1));
        mx0 = fmaxf(mx0, __shfl_xor_sync(0xffffffffu, mx0, 2));
        mx1 = fmaxf(mx1, __shfl_xor_sync(0xffffffffu, mx1, 1));
        mx1 = fmaxf(mx1, __shfl_xor_sync(0xffffffffu, mx1, 2));
        const float mn0 = fmaxf(mi0, mx0), mn1 = fmaxf(mi1, mx1);
        const float al0 = __expf(mi0 - mn0), al1 = __expf(mi1 - mn1);
        mi0 = mn0; mi1 = mn1;
        float sum0 = 0.f, sum1 = 0.f;
        #pragma unroll
        for (int nt = 0; nt < 16; nt++) {
            s[nt][0] = __expf(s[nt][0] - mn0);
            s[nt][1] = __expf(s[nt][1] - mn0);
            s[nt][2] = __expf(s[nt][2] - mn1);
            s[nt][3] = __expf(s[nt][3] - mn1);
            sum0 += s[nt][0] + s[nt][1];
            sum1 += s[nt][2] + s[nt][3];
        }
        sum0 += __shfl_xor_sync(0xffffffffu, sum0, 1);
        sum0 += __shfl_xor_sync(0xffffffffu, sum0, 2);
        sum1 += __shfl_xor_sync(0xffffffffu, sum1, 1);
        sum1 += __shfl_xor_sync(0xffffffffu, sum1, 2);
        li0 = li0 * al0 + sum0;
        li1 = li1 * al1 + sum1;
        #pragma unroll
        for (int i = 0; i < 8; i++) {
            onn[i][0] *= al0; onn[i][1] *= al0;
            onn[i][2] *= al1; onn[i][3] *= al1;
        }

        // ---- O += P @ V (P from registers, split; V from smem trans) ----
        #pragma unroll
        for (int ks2 = 0; ks2 < 8; ks2++) {
            uint32_t ph[4], pl[4];
            split2(s[2*ks2][0],   s[2*ks2][1],   ph[0], pl[0]);
            split2(s[2*ks2][2],   s[2*ks2][3],   ph[1], pl[1]);
            split2(s[2*ks2+1][0], s[2*ks2+1][1], ph[2], pl[2]);
            split2(s[2*ks2+1][2], s[2*ks2+1][3], ph[3], pl[3]);
            const int krow = ks2 * 16 + (lane & 15);
            #pragma unroll
            for (int nt2 = 0; nt2 < 8; nt2++) {
                const uint32_t ad = sb + 65536 + krow * 128 +
                                    ((nt2 ^ (krow & 7)) << 4);
                uint32_t vh2[2], vl2[2];
                ldsm_x2t(vh2, ad);
                ldsm_x2t(vl2, ad + 16384);
                mma16816(onn[nt2], ph, vh2[0], vh2[1]);
                mma16816(onn[nt2], ph, vl2[0], vl2[1]);
                mma16816(onn[nt2], pl, vh2[0], vh2[1]);
            }
        }
    }

    // ---- epilogue: y[b, q, h*64+d] as bf16 hi/lo ----
    const float inv0 = 1.f / li0, inv1 = 1.f / li1;
    const int r0g = q0 + wid * 16 + (lane >> 2);
    #pragma unroll
    for (int nt2 = 0; nt2 < 8; nt2++) {
        const int c = h * HS_ + nt2 * 8 + 2 * (lane & 3);
        uint32_t hi, lo;
        const size_t o0 = (size_t)(b * T_ + r0g) * C_ + c;
        split2(onn[nt2][0] * inv0, onn[nt2][1] * inv0, hi, lo);
        *(uint32_t*)(g_yhi + o0) = hi;
        *(uint32_t*)(g_ylo + o0) = lo;
        const size_t o1 = (size_t)(b * T_ + r0g + 8) * C_ + c;
        split2(onn[nt2][2] * inv1, onn[nt2][3] * inv1, hi, lo);
        *(uint32_t*)(g_yhi + o1) = hi;
        *(uint32_t*)(g_ylo + o1) = lo;
    }
}

// ---------------------------------------------------------------------------
extern "C" void kernel_launch(void* const* d_in, const int* in_sizes, int n_in,
                              void* d_out, int out_size)
{
    (void)in_sizes; (void)n_in; (void)out_size;
    const float* x      = (const float*)d_in[0];
    const float* w_u_b  = (const float*)d_in[2];
    const float* w_v_b  = (const float*)d_in[4];
    const float* proj_b = (const float*)d_in[6];
    float* out = (float*)d_out;

    cudaFuncSetAttribute(gemm_mma<0>,
                         cudaFuncAttributeMaxDynamicSharedMemorySize, GEMM_SMEM_BYTES);
    cudaFuncSetAttribute(gemm_mma<1>,
                         cudaFuncAttributeMaxDynamicSharedMemorySize, GEMM_SMEM_BYTES);
    cudaFuncSetAttribute(gemm_mma<2>,
                         cudaFuncAttributeMaxDynamicSharedMemorySize, GEMM_SMEM_BYTES);
    cudaFuncSetAttribute(attn_mma,
                         cudaFuncAttributeMaxDynamicSharedMemorySize, ATTN_SMEM);

    const int n4x = (M_TOT * C_) / 4;
    const int n4w = (C_ * C_) / 4;

    split_kernel<0><<<(n4x + 255) / 256, 256>>>(x, n4x);
    split_kernel<1><<<(n4w + 255) / 256, 256>>>((const float*)d_in[1], n4w);
    split_kernel<2><<<(n4w + 255) / 256, 256>>>((const float*)d_in[3], n4w);
    split_kernel<3><<<(n4w + 255) / 256, 256>>>((const float*)d_in[5], n4w);

    dim3 ggrid(C_ / 128, M_TOT / 128);   // (6, 32)
    gemm_mma<0><<<ggrid, 256, GEMM_SMEM_BYTES>>>(w_u_b, nullptr);   // u (scaled)
    gemm_mma<1><<<ggrid, 256, GEMM_SMEM_BYTES>>>(w_v_b, nullptr);   // v

    attn_mma<<<dim3(T_/128, B_*H_), 256, ATTN_SMEM>>>();            // y (bf16 hi/lo)

    gemm_mma<2><<<ggrid, 256, GEMM_SMEM_BYTES>>>(proj_b, out);      // out
}

// round 5
// speedup vs baseline: 3.0038x; 1.2407x over previous
#include <cuda_runtime.h>
#include <cuda_bf16.h>
#include <math.h>
#include <stdint.h>

#define B_   2
#define T_   2048
#define C_   768
#define H_   12
#define HS_  64
#define M_TOT (B_*T_)            // 4096
#define SCALE_F 0.03608439182435161f   // 1/sqrt(768)

// ---------------- scratch (device globals) ----------------------------------
__device__ __nv_bfloat16 g_xhi[M_TOT*C_], g_xlo[M_TOT*C_];
__device__ __nv_bfloat16 g_yhi[M_TOT*C_], g_ylo[M_TOT*C_];
__device__ __nv_bfloat16 g_uhi[M_TOT*C_], g_ulo[M_TOT*C_];  // scaled Q, [b,h,t,hs]
__device__ __nv_bfloat16 g_vhi[M_TOT*C_], g_vlo[M_TOT*C_];  // V, [b,h,t,hs]
__device__ __nv_bfloat16 g_wuhi[C_*C_], g_wulo[C_*C_];
__device__ __nv_bfloat16 g_wvhi[C_*C_], g_wvlo[C_*C_];
__device__ __nv_bfloat16 g_wphi[C_*C_], g_wplo[C_*C_];

// ---------------------------------------------------------------------------
__device__ __forceinline__ uint32_t smem_u32(const void* p) {
    uint32_t a;
    asm("{ .reg .u64 t; cvta.to.shared.u64 t, %1; cvt.u32.u64 %0, t; }"
        : "=r"(a) : "l"(p));
    return a;
}
__device__ __forceinline__ void ldsm_x4(uint32_t (&r)[4], uint32_t addr) {
    asm volatile("ldmatrix.sync.aligned.m8n8.x4.shared.b16 {%0,%1,%2,%3}, [%4];"
        : "=r"(r[0]), "=r"(r[1]), "=r"(r[2]), "=r"(r[3]) : "r"(addr));
}
__device__ __forceinline__ void ldsm_x2t(uint32_t (&r)[2], uint32_t addr) {
    asm volatile("ldmatrix.sync.aligned.m8n8.x2.trans.shared.b16 {%0,%1}, [%2];"
        : "=r"(r[0]), "=r"(r[1]) : "r"(addr));
}
__device__ __forceinline__ void mma16816(float (&d)[4], const uint32_t (&a)[4],
                                         uint32_t b0, uint32_t b1) {
    asm volatile(
        "mma.sync.aligned.m16n8k16.row.col.f32.bf16.bf16.f32 "
        "{%0,%1,%2,%3}, {%4,%5,%6,%7}, {%8,%9}, {%0,%1,%2,%3};"
        : "+f"(d[0]), "+f"(d[1]), "+f"(d[2]), "+f"(d[3])
        : "r"(a[0]), "r"(a[1]), "r"(a[2]), "r"(a[3]), "r"(b0), "r"(b1));
}
__device__ __forceinline__ void cp16(uint32_t dst, const void* src) {
    asm volatile("cp.async.cg.shared.global [%0], [%1], 16;"
                 :: "r"(dst), "l"(src));
}
#define CP_COMMIT() asm volatile("cp.async.commit_group;" ::: "memory")
#define CP_WAIT0()  asm volatile("cp.async.wait_group 0;" ::: "memory")
#define CP_WAIT1()  asm volatile("cp.async.wait_group 1;" ::: "memory")

__device__ __forceinline__ void split2(float f0, float f1, uint32_t& hi, uint32_t& lo) {
    __nv_bfloat16 h0 = __float2bfloat16(f0), h1 = __float2bfloat16(f1);
    __nv_bfloat16 l0 = __float2bfloat16(f0 - __bfloat162float(h0));
    __nv_bfloat16 l1 = __float2bfloat16(f1 - __bfloat162float(h1));
    __nv_bfloat162 Hp = __halves2bfloat162(h0, h1), Lp = __halves2bfloat162(l0, l1);
    hi = *(uint32_t*)&Hp; lo = *(uint32_t*)&Lp;
}

// ---------------------------------------------------------------------------
// merged fp32 -> bf16 hi/lo split for x, w_u, w_v, w_p
// ---------------------------------------------------------------------------
#define N4X ((M_TOT*C_)/4)
#define N4W ((C_*C_)/4)

__global__ void split_all(const float* __restrict__ x, const float* __restrict__ wu,
                          const float* __restrict__ wv, const float* __restrict__ wp)
{
    int i = blockIdx.x * blockDim.x + threadIdx.x;
    const float* src;
    __nv_bfloat16 *hi, *lo;
    int j;
    if (i < N4X)                 { src = x;  hi = g_xhi;  lo = g_xlo;  j = i; }
    else if (i < N4X + N4W)      { src = wu; hi = g_wuhi; lo = g_wulo; j = i - N4X; }
    else if (i < N4X + 2*N4W)    { src = wv; hi = g_wvhi; lo = g_wvlo; j = i - N4X - N4W; }
    else                         { src = wp; hi = g_wphi; lo = g_wplo; j = i - N4X - 2*N4W; }
    float4 v = reinterpret_cast<const float4*>(src)[j];
    uint32_t h0, l0, h1, l1;
    split2(v.x, v.y, h0, l0);
    split2(v.z, v.w, h1, l1);
    reinterpret_cast<uint32_t*>(hi)[j*2+0] = h0;
    reinterpret_cast<uint32_t*>(hi)[j*2+1] = h1;
    reinterpret_cast<uint32_t*>(lo)[j*2+0] = l0;
    reinterpret_cast<uint32_t*>(lo)[j*2+1] = l1;
}

// ---------------------------------------------------------------------------
// Pipelined HMMA GEMM. CTA 128x128, 8 warps (64x32), K-chunk 32, 2 stages.
// stage (32KB): Ahi@0 Alo@8K Bhi@16K Blo@24K; rows = 64B, swizzle
//   off(r,c16) = r*64 + ((c16 ^ ((r>>1)&3)) << 4)
// MODE 0: fused u/v (blockIdx.z: 0 -> u scaled, 1 -> v), A = x
// MODE 1: proj, A = y, write fp32 out
// ---------------------------------------------------------------------------
#define GEMM_SMEM_BYTES 65536

__device__ __forceinline__ int sw64(int r, int c) {
    return r * 64 + ((c ^ ((r >> 1) & 3)) << 4);
}

template<int MODE>
__global__ __launch_bounds__(256, 2)
void gemm_pipe(const float* __restrict__ bias0, const float* __restrict__ bias1,
               float* __restrict__ outp)
{
    extern __shared__ char sm[];
    const uint32_t sb = smem_u32(sm);

    const int z = (MODE == 0) ? blockIdx.z : 0;
    const __nv_bfloat16* Ahi = (MODE == 1) ? g_yhi : g_xhi;
    const __nv_bfloat16* Alo = (MODE == 1) ? g_ylo : g_xlo;
    const __nv_bfloat16* Bhi = (MODE == 1) ? g_wphi : (z ? g_wvhi : g_wuhi);
    const __nv_bfloat16* Blo = (MODE == 1) ? g_wplo : (z ? g_wvlo : g_wulo);
    const float* bias = (MODE == 1) ? bias0 : (z ? bias1 : bias0);

    const int tid = threadIdx.x;
    const int wid = tid >> 5, lane = tid & 31;
    const int m0 = blockIdx.y * 128;
    const int n0 = blockIdx.x * 128;
    const int wm = (wid & 1) * 64;
    const int wn = (wid >> 1) * 32;

    float acc[4][4][4];
    #pragma unroll
    for (int a = 0; a < 4; a++)
        #pragma unroll
        for (int b = 0; b < 4; b++)
            #pragma unroll
            for (int c = 0; c < 4; c++) acc[a][b][c] = 0.f;

    // global-load mapping: per array 512 uint4 = 128 rows x 4 chunks
    int ldr[2], ldo[2], ldc[2];
    #pragma unroll
    for (int it = 0; it < 2; it++) {
        int f = tid + it * 256;
        ldr[it] = f >> 2; ldc[it] = f & 3;
        ldo[it] = sw64(ldr[it], ldc[it]);
    }

    auto issue = [&](int kc, int st) {
        const uint32_t s = sb + st * 32768;
        const int kcol = kc * 32;
        #pragma unroll
        for (int it = 0; it < 2; it++) {
            const size_t ga = (size_t)(m0 + ldr[it]) * C_ + kcol + ldc[it] * 8;
            const size_t gb = (size_t)(n0 + ldr[it]) * C_ + kcol + ldc[it] * 8;
            cp16(s + ldo[it],          Ahi + ga);
            cp16(s + 8192  + ldo[it],  Alo + ga);
            cp16(s + 16384 + ldo[it],  Bhi + gb);
            cp16(s + 24576 + ldo[it],  Blo + gb);
        }
        CP_COMMIT();
    };

    const int a_r = lane & 15, a_co = lane >> 4;
    const int b_r = (lane & 7) + ((lane >> 4) << 3), b_co = (lane >> 3) & 1;

    issue(0, 0);
    for (int kc = 0; kc < 24; kc++) {
        if (kc + 1 < 24) { issue(kc + 1, (kc + 1) & 1); CP_WAIT1(); }
        else             { CP_WAIT0(); }
        __syncthreads();
        const uint32_t s = sb + (kc & 1) * 32768;
        #pragma unroll
        for (int ks = 0; ks < 2; ks++) {
            uint32_t bhi[2][4], blo[2][4];
            #pragma unroll
            for (int bt = 0; bt < 2; bt++) {
                const int row = wn + bt * 16 + b_r;
                const uint32_t ad = s + 16384 + sw64(row, ks * 2 + b_co);
                ldsm_x4(bhi[bt], ad);
                ldsm_x4(blo[bt], ad + 8192);
            }
            #pragma unroll
            for (int mt = 0; mt < 4; mt++) {
                const int row = wm + mt * 16 + a_r;
                const uint32_t ad = s + sw64(row, ks * 2 + a_co);
                uint32_t ahi[4], alo[4];
                ldsm_x4(ahi, ad);
                ldsm_x4(alo, ad + 8192);
                #pragma unroll
                for (int nt = 0; nt < 4; nt++) {
                    const int bt = nt >> 1, hf = (nt & 1) * 2;
                    mma16816(acc[mt][nt], ahi, bhi[bt][hf], bhi[bt][hf + 1]);
                    mma16816(acc[mt][nt], ahi, blo[bt][hf], blo[bt][hf + 1]);
                    mma16816(acc[mt][nt], alo, bhi[bt][hf], bhi[bt][hf + 1]);
                }
            }
        }
        __syncthreads();
    }

    const int er = lane >> 2, ec = (lane & 3) * 2;
    #pragma unroll
    for (int mt = 0; mt < 4; mt++) {
        #pragma unroll
        for (int nt = 0; nt < 4; nt++) {
            const int n = n0 + wn + nt * 8 + ec;
            const float b0 = bias[n], b1 = bias[n + 1];
            #pragma unroll
            for (int half = 0; half < 2; half++) {
                const int m = m0 + wm + mt * 16 + er + half * 8;
                float v0 = acc[mt][nt][half * 2 + 0] + b0;
                float v1 = acc[mt][nt][half * 2 + 1] + b1;
                if (MODE == 1) {
                    *(float2*)(outp + (size_t)m * C_ + n) = make_float2(v0, v1);
                } else {
                    if (z == 0) { v0 *= SCALE_F; v1 *= SCALE_F; }
                    const int bb = m >> 11, t = m & (T_ - 1);
                    const int hh = n >> 6, hs = n & 63;
                    uint32_t hi, lo;
                    split2(v0, v1, hi, lo);
                    __nv_bfloat16* dhi = z ? g_vhi : g_uhi;
                    __nv_bfloat16* dlo = z ? g_vlo : g_ulo;
                    const size_t off = (((size_t)(bb * H_ + hh)) * T_ + t) * HS_ + hs;
                    *(uint32_t*)(dhi + off) = hi;
                    *(uint32_t*)(dlo + off) = lo;
                }
            }
        }
    }
}

// ---------------------------------------------------------------------------
// HMMA flash attention, split bf16, cp.async double-buffered K/V,
// Q fragments hoisted to registers.
// smem: Qhi@0 Qlo@16K; stage s @ 32K + s*64K: Khi@0 Klo@16K Vhi@32K Vlo@48K
// ---------------------------------------------------------------------------
#define ATTN_SMEM (32768 + 2*65536)

__global__ __launch_bounds__(256, 1)
void attn_mma()
{
    extern __shared__ char sm[];
    const uint32_t sb = smem_u32(sm);
    const int tid = threadIdx.x, wid = tid >> 5, lane = tid & 31;
    const int qt = (int)(gridDim.x - 1) - (int)blockIdx.x;  // longest first
    const int bh = blockIdx.y;
    const int b = bh / H_, h = bh % H_;
    const int q0 = qt * 128;

    const __nv_bfloat16* Kh = g_xhi + (size_t)b * T_ * C_ + h * HS_;
    const __nv_bfloat16* Kl = g_xlo + (size_t)b * T_ * C_ + h * HS_;
    const __nv_bfloat16* Vh = g_vhi + (size_t)bh * T_ * HS_;
    const __nv_bfloat16* Vl = g_vlo + (size_t)bh * T_ * HS_;
    const __nv_bfloat16* Qh = g_uhi + (size_t)bh * T_ * HS_;
    const __nv_bfloat16* Ql = g_ulo + (size_t)bh * T_ * HS_;

    int ldr[4], ldo[4], ldc[4];
    #pragma unroll
    for (int it = 0; it < 4; it++) {
        int f = tid + it * 256;
        int r = f >> 3, ch = f & 7;
        ldr[it] = r; ldc[it] = ch;
        ldo[it] = r * 128 + ((ch ^ (r & 7)) << 4);
    }

    // stage Q (group 0)
    #pragma unroll
    for (int it = 0; it < 4; it++) {
        const size_t g = (size_t)(q0 + ldr[it]) * HS_ + ldc[it] * 8;
        cp16(sb + ldo[it],         Qh + g);
        cp16(sb + 16384 + ldo[it], Ql + g);
    }
    CP_COMMIT();

    auto issue_kv = [&](int kt, int st) {
        const int k0 = kt * 128;
        const uint32_t s = sb + 32768 + st * 65536;
        #pragma unroll
        for (int it = 0; it < 4; it++) {
            const size_t gk = (size_t)(k0 + ldr[it]) * C_ + ldc[it] * 8;
            const size_t gv = (size_t)(k0 + ldr[it]) * HS_ + ldc[it] * 8;
            cp16(s + ldo[it],         Kh + gk);
            cp16(s + 16384 + ldo[it], Kl + gk);
            cp16(s + 32768 + ldo[it], Vh + gv);
            cp16(s + 49152 + ldo[it], Vl + gv);
        }
        CP_COMMIT();
    };

    issue_kv(0, 0);

    const int a_r = lane & 15, a_co = lane >> 4;
    const int b_r = (lane & 7) + ((lane >> 4) << 3), b_co = (lane >> 3) & 1;

    uint32_t qfh[4][4], qfl[4][4];   // hoisted Q fragments per ks
    float onn[8][4];
    #pragma unroll
    for (int i = 0; i < 8; i++)
        #pragma unroll
        for (int j = 0; j < 4; j++) onn[i][j] = 0.f;
    float mi0 = -INFINITY, mi1 = -INFINITY, li0 = 0.f, li1 = 0.f;

    for (int kt = 0; kt <= qt; kt++) {
        if (kt + 1 <= qt) { issue_kv(kt + 1, (kt + 1) & 1); CP_WAIT1(); }
        else              { CP_WAIT0(); }
        __syncthreads();

        if (kt == 0) {   // hoist Q fragments once
            const int row = wid * 16 + a_r;
            #pragma unroll
            for (int ks = 0; ks < 4; ks++) {
                const uint32_t ad = sb + row * 128 +
                                    (((ks * 2 + a_co) ^ (row & 7)) << 4);
                ldsm_x4(qfh[ks], ad);
                ldsm_x4(qfl[ks], ad + 16384);
            }
        }

        const uint32_t s0 = sb + 32768 + (kt & 1) * 65536;

        // ---- S = Q @ K^T ----
        float s[16][4];
        #pragma unroll
        for (int i = 0; i < 16; i++)
            #pragma unroll
            for (int j = 0; j < 4; j++) s[i][j] = 0.f;

        #pragma unroll
        for (int ks = 0; ks < 4; ks++) {
            #pragma unroll
            for (int bt = 0; bt < 8; bt++) {
                const int row = bt * 16 + b_r;
                const uint32_t ad = s0 + row * 128 +
                                    (((ks * 2 + b_co) ^ (row & 7)) << 4);
                uint32_t kh[4], kl[4];
                ldsm_x4(kh, ad);
                ldsm_x4(kl, ad + 16384);
                #pragma unroll
                for (int hf = 0; hf < 2; hf++) {
                    const int nt = bt * 2 + hf;
                    mma16816(s[nt], qfh[ks], kh[hf*2], kh[hf*2+1]);
                    mma16816(s[nt], qfh[ks], kl[hf*2], kl[hf*2+1]);
                    mma16816(s[nt], qfl[ks], kh[hf*2], kh[hf*2+1]);
                }
            }
        }

        // ---- causal mask (diagonal tile only) ----
        if (kt == qt) {
            const int r0 = wid * 16 + (lane >> 2);
            #pragma unroll
            for (int nt = 0; nt < 16; nt++) {
                const int c = nt * 8 + 2 * (lane & 3);
                if (c     > r0)     s[nt][0] = -INFINITY;
                if (c + 1 > r0)     s[nt][1] = -INFINITY;
                if (c     > r0 + 8) s[nt][2] = -INFINITY;
                if (c + 1 > r0 + 8) s[nt][3] = -INFINITY;
            }
        }

        // ---- online softmax ----
        float mx0 = -INFINITY, mx1 = -INFINITY;
        #pragma unroll
        for (int nt = 0; nt < 16; nt++) {
            mx0 = fmaxf(mx0, fmaxf(s[nt][0], s[nt][1]));
            mx1 = fmaxf(mx1, fmaxf(s[nt][2], s[nt][3]));
        }
        mx0 = fmaxf(mx0, __shfl_xor_sync(0xffffffffu, mx0, 1));
        mx0 = fmaxf(mx0, __shfl_xor_sync(0xffffffffu, mx0, 2));
        mx1 = fmaxf(mx1, __shfl_xor_sync(0xffffffffu, mx1, 1));
        mx1 = fmaxf(mx1, __shfl_xor_sync(0xffffffffu, mx1, 2));
        const float mn0 = fmaxf(mi0, mx0), mn1 = fmaxf(mi1, mx1);
        const float al0 = __expf(mi0 - mn0), al1 = __expf(mi1 - mn1);
        mi0 = mn0; mi1 = mn1;
        float sum0 = 0.f, sum1 = 0.f;
        #pragma unroll
        for (int nt = 0; nt < 16; nt++) {
            s[nt][0] = __expf(s[nt][0] - mn0);
            s[nt][1] = __expf(s[nt][1] - mn0);
            s[nt][2] = __expf(s[nt][2] - mn1);
            s[nt][3] = __expf(s[nt][3] - mn1);
            sum0 += s[nt][0] + s[nt][1];
            sum1 += s[nt][2] + s[nt][3];
        }
        sum0 += __shfl_xor_sync(0xffffffffu, sum0, 1);
        sum0 += __shfl_xor_sync(0xffffffffu, sum0, 2);
        sum1 += __shfl_xor_sync(0xffffffffu, sum1, 1);
        sum1 += __shfl_xor_sync(0xffffffffu, sum1, 2);
        li0 = li0 * al0 + sum0;
        li1 = li1 * al1 + sum1;
        #pragma unroll
        for (int i = 0; i < 8; i++) {
            onn[i][0] *= al0; onn[i][1] *= al0;
            onn[i][2] *= al1; onn[i][3] *= al1;
        }

        // ---- O += P @ V ----
        #pragma unroll
        for (int ks2 = 0; ks2 < 8; ks2++) {
            uint32_t ph[4], pl[4];
            split2(s[2*ks2][0],   s[2*ks2][1],   ph[0], pl[0]);
            split2(s[2*ks2][2],   s[2*ks2][3],   ph[1], pl[1]);
            split2(s[2*ks2+1][0], s[2*ks2+1][1], ph[2], pl[2]);
            split2(s[2*ks2+1][2], s[2*ks2+1][3], ph[3], pl[3]);
            const int krow = ks2 * 16 + (lane & 15);
            #pragma unroll
            for (int nt2 = 0; nt2 < 8; nt2++) {
                const uint32_t ad = s0 + 32768 + krow * 128 +
                                    ((nt2 ^ (krow & 7)) << 4);
                uint32_t vh2[2], vl2[2];
                ldsm_x2t(vh2, ad);
                ldsm_x2t(vl2, ad + 16384);
                mma16816(onn[nt2], ph, vh2[0], vh2[1]);
                mma16816(onn[nt2], ph, vl2[0], vl2[1]);
                mma16816(onn[nt2], pl, vh2[0], vh2[1]);
            }
        }
        __syncthreads();
    }

    // ---- epilogue: y as bf16 hi/lo ----
    const float inv0 = 1.f / li0, inv1 = 1.f / li1;
    const int r0g = q0 + wid * 16 + (lane >> 2);
    #pragma unroll
    for (int nt2 = 0; nt2 < 8; nt2++) {
        const int c = h * HS_ + nt2 * 8 + 2 * (lane & 3);
        uint32_t hi, lo;
        const size_t o0 = (size_t)(b * T_ + r0g) * C_ + c;
        split2(onn[nt2][0] * inv0, onn[nt2][1] * inv0, hi, lo);
        *(uint32_t*)(g_yhi + o0) = hi;
        *(uint32_t*)(g_ylo + o0) = lo;
        const size_t o1 = (size_t)(b * T_ + r0g + 8) * C_ + c;
        split2(onn[nt2][2] * inv1, onn[nt2][3] * inv1, hi, lo);
        *(uint32_t*)(g_yhi + o1) = hi;
        *(uint32_t*)(g_ylo + o1) = lo;
    }
}

// ---------------------------------------------------------------------------
extern "C" void kernel_launch(void* const* d_in, const int* in_sizes, int n_in,
                              void* d_out, int out_size)
{
    (void)in_sizes; (void)n_in; (void)out_size;
    const float* x      = (const float*)d_in[0];
    const float* w_u_w  = (const float*)d_in[1];
    const float* w_u_b  = (const float*)d_in[2];
    const float* w_v_w  = (const float*)d_in[3];
    const float* w_v_b  = (const float*)d_in[4];
    const float* proj_w = (const float*)d_in[5];
    const float* proj_b = (const float*)d_in[6];
    float* out = (float*)d_out;

    cudaFuncSetAttribute(gemm_pipe<0>,
                         cudaFuncAttributeMaxDynamicSharedMemorySize, GEMM_SMEM_BYTES);
    cudaFuncSetAttribute(gemm_pipe<1>,
                         cudaFuncAttributeMaxDynamicSharedMemorySize, GEMM_SMEM_BYTES);
    cudaFuncSetAttribute(attn_mma,
                         cudaFuncAttributeMaxDynamicSharedMemorySize, ATTN_SMEM);

    const int ntot = N4X + 3 * N4W;
    split_all<<<(ntot + 255) / 256, 256>>>(x, w_u_w, w_v_w, proj_w);

    gemm_pipe<0><<<dim3(6, 32, 2), 256, GEMM_SMEM_BYTES>>>(w_u_b, w_v_b, nullptr);

    attn_mma<<<dim3(T_/128, B_*H_), 256, ATTN_SMEM>>>();

    gemm_pipe<1><<<dim3(6, 32, 1), 256, GEMM_SMEM_BYTES>>>(proj_b, nullptr, out);
}